// round 7
// baseline (speedup 1.0000x reference)
#include <cuda_runtime.h>
#include <cuda_bf16.h>
#include <cuda_fp16.h>
#include <stdint.h>

// fp16 side-table of updated type rows with the big additive constant removed:
//   delta[t][d] = emb[t][d] + msg2[t][d]            (range ~ +-50, fp16-safe)
// full row    = delta + (n_ent - deg2)
// Capacity: 8192 type rows x 128 dims (2 MB). Row layout: 32 x uint2 (4 halves
// per lane), matching the float4 lane mapping (lane covers dims [4L, 4L+4)).
#define TYP16_MAX_ROWS 8192
__device__ static uint2 g_typ16[TYP16_MAX_ROWS * 32];

// ===========================================================================
// Phase 1 (sub2), fast path: deg2==64, D==128.
// One 128-thread block per type column. Warp w sums 16 of the 64 edge rows
// with float4 loads, smem reduce, warp 0 writes the fp32 row to `out` AND the
// fp16 delta row to g_typ16.
// ===========================================================================
__global__ void sub2_f16_kernel(const float4* __restrict__ emb4,
                                const int*    __restrict__ s2r,
                                const int*    __restrict__ ls,
                                const int*    __restrict__ rc,
                                float4*       __restrict__ out4,
                                int n_ent)
{
    __shared__ int    rows[64];
    __shared__ float4 part[3][32];

    const int c    = blockIdx.x;
    const int t    = threadIdx.x;
    const int lane = t & 31;
    const int w    = t >> 5;

    if (t < 64) rows[t] = ls[__ldg(s2r + c * 64 + t)];
    __syncthreads();

    float4 acc = make_float4(0.f, 0.f, 0.f, 0.f);
    #pragma unroll
    for (int e = 0; e < 16; ++e) {
        const int r = rows[e * 4 + w];
        float4 v = __ldg(emb4 + (size_t)r * 32 + lane);
        acc.x += v.x; acc.y += v.y; acc.z += v.z; acc.w += v.w;
    }

    if (w > 0) part[w - 1][lane] = acc;
    __syncthreads();

    if (w == 0) {
        #pragma unroll
        for (int i = 0; i < 3; ++i) {
            float4 p = part[i][lane];
            acc.x += p.x; acc.y += p.y; acc.z += p.z; acc.w += p.w;
        }
        const int tr = __ldg(rc + c);
        float4 iv = __ldg(emb4 + (size_t)tr * 32 + lane);
        // delta (no base constant) -> fp16 side table
        float4 dlt;
        dlt.x = iv.x + acc.x;
        dlt.y = iv.y + acc.y;
        dlt.z = iv.z + acc.z;
        dlt.w = iv.w + acc.w;
        __half2 h0 = __floats2half2_rn(dlt.x, dlt.y);
        __half2 h1 = __floats2half2_rn(dlt.z, dlt.w);
        uint2 u;
        u.x = *reinterpret_cast<const unsigned int*>(&h0);
        u.y = *reinterpret_cast<const unsigned int*>(&h1);
        g_typ16[(size_t)(tr - n_ent) * 32 + lane] = u;
        // full fp32 row -> output
        const float base = (float)n_ent - 64.0f;
        float4 r;
        r.x = dlt.x + base; r.y = dlt.y + base;
        r.z = dlt.z + base; r.w = dlt.w + base;
        out4[(size_t)tr * 32 + lane] = r;
    }
}

// Generic fallback (any deg2 / D).
__global__ void sub2_gen_kernel(const float* __restrict__ emb,
                                const int*   __restrict__ s2r,
                                const int*   __restrict__ ls,
                                const int*   __restrict__ rc,
                                float*       __restrict__ out,
                                int deg2, int n_ent, int D)
{
    extern __shared__ int rows[];
    const int c = blockIdx.x;
    for (int i = threadIdx.x; i < deg2; i += blockDim.x)
        rows[i] = ls[s2r[(size_t)c * deg2 + i]];
    __syncthreads();

    const int d = threadIdx.x;
    if (d >= D) return;
    float acc = (float)n_ent - (float)deg2;
    #pragma unroll 8
    for (int e = 0; e < deg2; ++e)
        acc += emb[(size_t)rows[e] * D + d];
    const int t = rc[c];
    out[(size_t)t * D + d] = emb[(size_t)t * D + d] + acc;
}

// ===========================================================================
// Phase 2 (sub3), fast path: deg2==64, deg3==4, D==128.
// One warp per entity. Type-row gathers read the fp16 delta table (half the
// L1 wavefronts of fp32; 256 KB -> near-L1-resident). The exact constant
// (n_typ-4) + 4*(n_ent-64) is added back in fp32. Entity rows stream with
// evict-first hints so they don't pollute the hot table.
// ===========================================================================
__global__ void sub3_f16_kernel(const float4* __restrict__ emb4,
                                const int4*   __restrict__ s3r4,
                                const int*    __restrict__ lc,
                                const int*    __restrict__ rs,
                                float4*       out4,
                                int n_typ, int n_ent)
{
    const int ent  = blockIdx.x * 8 + (threadIdx.x >> 5);
    const int lane = threadIdx.x & 31;
    if (ent >= n_ent) return;

    const int4 e4 = __ldg(s3r4 + ent);
    const int tr  = __ldg(rs + ent);
    const int t0 = __ldg(lc + e4.x) - n_ent;
    const int t1 = __ldg(lc + e4.y) - n_ent;
    const int t2 = __ldg(lc + e4.z) - n_ent;
    const int t3 = __ldg(lc + e4.w) - n_ent;

    // Streaming entity row read started early (independent chain).
    float4 iv = __ldcs(emb4 + (size_t)tr * 32 + lane);

    const uint2 a0 = g_typ16[(size_t)t0 * 32 + lane];
    const uint2 a1 = g_typ16[(size_t)t1 * 32 + lane];
    const uint2 a2 = g_typ16[(size_t)t2 * 32 + lane];
    const uint2 a3 = g_typ16[(size_t)t3 * 32 + lane];

    float2 lo = make_float2(0.f, 0.f), hi = make_float2(0.f, 0.f);
    {
        float2 p, q;
        p = __half22float2(*reinterpret_cast<const __half2*>(&a0.x));
        q = __half22float2(*reinterpret_cast<const __half2*>(&a0.y));
        lo.x += p.x; lo.y += p.y; hi.x += q.x; hi.y += q.y;
        p = __half22float2(*reinterpret_cast<const __half2*>(&a1.x));
        q = __half22float2(*reinterpret_cast<const __half2*>(&a1.y));
        lo.x += p.x; lo.y += p.y; hi.x += q.x; hi.y += q.y;
        p = __half22float2(*reinterpret_cast<const __half2*>(&a2.x));
        q = __half22float2(*reinterpret_cast<const __half2*>(&a2.y));
        lo.x += p.x; lo.y += p.y; hi.x += q.x; hi.y += q.y;
        p = __half22float2(*reinterpret_cast<const __half2*>(&a3.x));
        q = __half22float2(*reinterpret_cast<const __half2*>(&a3.y));
        lo.x += p.x; lo.y += p.y; hi.x += q.x; hi.y += q.y;
    }

    // acc = (n_typ - deg3) + sum_i [delta_i + (n_ent - deg2)]
    const float baseAll = (float)(n_typ - 4) + 4.0f * ((float)n_ent - 64.0f);
    const float inv = 0.2f;  // 1/(1+deg3)
    float4 r;
    r.x = iv.x * (1.0f - (baseAll + lo.x) * inv);
    r.y = iv.y * (1.0f - (baseAll + lo.y) * inv);
    r.z = iv.z * (1.0f - (baseAll + hi.x) * inv);
    r.w = iv.w * (1.0f - (baseAll + hi.y) * inv);
    __stcs(out4 + (size_t)tr * 32 + lane, r);
}

// Generic fallback (reads fp32 type rows from `out`).
__global__ void sub3_gen_kernel(const float* __restrict__ emb,
                                const int*   __restrict__ s3r,
                                const int*   __restrict__ lc,
                                const int*   __restrict__ rs,
                                float*       out,
                                int deg3, int n_typ, int n_ent, int D)
{
    const int tpe  = D >> 2;
    const int epb  = blockDim.x / tpe;
    const int ent  = blockIdx.x * epb + threadIdx.x / tpe;
    const int lane = threadIdx.x % tpe;
    if (ent >= n_ent) return;

    const float base = (float)n_typ - (float)deg3;
    float4 acc = make_float4(base, base, base, base);
    const int* er = s3r + (size_t)ent * deg3;
    const float4* out4 = (const float4*)out;
    for (int e = 0; e < deg3; ++e) {
        const int t = lc[er[e]];
        float4 v = out4[(size_t)t * tpe + lane];
        acc.x += v.x; acc.y += v.y; acc.z += v.z; acc.w += v.w;
    }
    const float inv = 1.0f / (1.0f + (float)deg3);
    const int t = rs[ent];
    float4 iv = ((const float4*)emb)[(size_t)t * tpe + lane];
    float4 r;
    r.x = iv.x * (1.0f - acc.x * inv);
    r.y = iv.y * (1.0f - acc.y * inv);
    r.z = iv.z * (1.0f - acc.z * inv);
    r.w = iv.w * (1.0f - acc.w * inv);
    ((float4*)out)[(size_t)t * tpe + lane] = r;
}

// ===========================================================================
// Inputs (metadata order):
//  0 all_node_embedding f32 [(n_ent+n_typ)*D]
//  1 sub2_row i32   2 sub2_col i32   3 sub3_row i32   4 sub3_col i32
//  5 left_specific i32 [n_ent]   6 right_common i32 [n_typ]
//  7 left_common  i32 [n_typ]    8 right_specific i32 [n_ent]
// Type rows U entity rows cover the whole output -> no copy kernel.
// ===========================================================================
extern "C" void kernel_launch(void* const* d_in, const int* in_sizes, int n_in,
                              void* d_out, int out_size)
{
    const float* emb = (const float*)d_in[0];
    const int*   s2r = (const int*)d_in[1];
    const int*   s3r = (const int*)d_in[3];
    const int*   ls  = (const int*)d_in[5];
    const int*   rc  = (const int*)d_in[6];
    const int*   lc  = (const int*)d_in[7];
    const int*   rs  = (const int*)d_in[8];
    float* out = (float*)d_out;

    const int n_ent = in_sizes[5];
    const int n_typ = in_sizes[7];
    const int D     = in_sizes[0] / (n_ent + n_typ);   // 128
    const int deg2  = in_sizes[1] / n_typ;             // 64
    const int deg3  = in_sizes[3] / n_ent;             // 4

    const bool fast = (deg2 == 64) && (deg3 == 4) && (D == 128) &&
                      (n_typ <= TYP16_MAX_ROWS);

    if (fast) {
        sub2_f16_kernel<<<n_typ, 128>>>(
            (const float4*)emb, s2r, ls, rc, (float4*)out, n_ent);
        const int grid = (n_ent + 7) / 8;
        sub3_f16_kernel<<<grid, 256>>>(
            (const float4*)emb, (const int4*)s3r, lc, rs, (float4*)out,
            n_typ, n_ent);
    } else {
        sub2_gen_kernel<<<n_typ, (D + 31) & ~31, deg2 * (int)sizeof(int)>>>(
            emb, s2r, ls, rc, out, deg2, n_ent, D);
        const int tpe = D >> 2;
        const int block = 256;
        const int epb = block / tpe;
        const int grid = (n_ent + epb - 1) / epb;
        sub3_gen_kernel<<<grid, block>>>(
            emb, s3r, lc, rs, out, deg3, n_typ, n_ent, D);
    }
}